// round 6
// baseline (speedup 1.0000x reference)
#include <cuda_runtime.h>
#include <math.h>

// ---------------- problem constants ----------------
#define BDIM   8
#define LDIM   1024
#define DDIM   1024
#define GG     4
#define HDIM   64
#define DKC    256          // D / G
#define NQKV   1536         // D + 2*DK
#define ML     (BDIM*LDIM)  // 8192 rows

// ---------------- scratch (__device__ globals; no allocs allowed) ----------
__device__ float g_qkv[(size_t)ML * NQKV];   // qkv projection output
__device__ float g_k  [(size_t)ML * DKC];    // conv'd k
__device__ float g_v  [(size_t)ML * DKC];    // conv'd v
__device__ float g_ctx[(size_t)ML * DDIM];   // attention context (pre W_out)

// ---------------- tiled SGEMM, double-buffered: C = A[MxK]*W[KxN] + bias ---
// 128x128 tile, BK=8, 8x8 microtile, 256 threads. Smem ping-pong: stores for
// tile i+1 go to the opposite buffer from the one tile i reads, so ONE
// barrier per iteration is sufficient.
__global__ __launch_bounds__(256) void sgemm_bias(
    const float* __restrict__ A, const float* __restrict__ W,
    const float* __restrict__ bias, float* __restrict__ C,
    int M, int N, int K)
{
    __shared__ float As[2][8][128];
    __shared__ float Bs[2][8][128];
    const int tid = threadIdx.x;
    const int bm = blockIdx.y * 128;
    const int bn = blockIdx.x * 128;
    const int ty = tid >> 4;      // 0..15 -> 8 rows each
    const int tx = tid & 15;      // 0..15 -> 8 cols each

    float acc[8][8];
#pragma unroll
    for (int i = 0; i < 8; i++)
#pragma unroll
        for (int j = 0; j < 8; j++) acc[i][j] = 0.f;

    const int aRow = tid >> 1;
    const int aK   = (tid & 1) * 4;
    const int bK   = tid >> 5;
    const int bC   = (tid & 31) * 4;

    const float* aPtr = A + (size_t)(bm + aRow) * K + aK;
    const float* bPtr = W + (size_t)bK * N + bn + bC;

    // preload tile 0
    {
        float4 av = *(const float4*)(aPtr);
        float4 bv = *(const float4*)(bPtr);
        As[0][aK + 0][aRow] = av.x;
        As[0][aK + 1][aRow] = av.y;
        As[0][aK + 2][aRow] = av.z;
        As[0][aK + 3][aRow] = av.w;
        *(float4*)(&Bs[0][bK][bC]) = bv;
    }
    __syncthreads();

    int buf = 0;
    for (int k0 = 0; k0 < K; k0 += 8) {
        const bool has_next = (k0 + 8) < K;
        float4 av, bv;
        if (has_next) {
            // issued ~512 FMA-instructions ahead of first use -> latency hidden
            av = *(const float4*)(aPtr + k0 + 8);
            bv = *(const float4*)(bPtr + (size_t)(k0 + 8) * N);
        }

#pragma unroll
        for (int k = 0; k < 8; k++) {
            float a[8], b[8];
            *(float4*)(a)     = *(const float4*)(&As[buf][k][ty * 8]);
            *(float4*)(a + 4) = *(const float4*)(&As[buf][k][ty * 8 + 4]);
            *(float4*)(b)     = *(const float4*)(&Bs[buf][k][tx * 8]);
            *(float4*)(b + 4) = *(const float4*)(&Bs[buf][k][tx * 8 + 4]);
#pragma unroll
            for (int i = 0; i < 8; i++)
#pragma unroll
                for (int j = 0; j < 8; j++) acc[i][j] += a[i] * b[j];
        }

        if (has_next) {
            const int nb = buf ^ 1;
            As[nb][aK + 0][aRow] = av.x;
            As[nb][aK + 1][aRow] = av.y;
            As[nb][aK + 2][aRow] = av.z;
            As[nb][aK + 3][aRow] = av.w;
            *(float4*)(&Bs[nb][bK][bC]) = bv;
            __syncthreads();
            buf = nb;
        }
    }

#pragma unroll
    for (int i = 0; i < 8; i++) {
        float* crow = C + (size_t)(bm + ty * 8 + i) * N + bn + tx * 8;
#pragma unroll
        for (int j4 = 0; j4 < 2; j4++) {
            float4 o;
            o.x = acc[i][j4 * 4 + 0] + bias[bn + tx * 8 + j4 * 4 + 0];
            o.y = acc[i][j4 * 4 + 1] + bias[bn + tx * 8 + j4 * 4 + 1];
            o.z = acc[i][j4 * 4 + 2] + bias[bn + tx * 8 + j4 * 4 + 2];
            o.w = acc[i][j4 * 4 + 3] + bias[bn + tx * 8 + j4 * 4 + 3];
            *(float4*)(crow + j4 * 4) = o;
        }
    }
}

// ---------------- grouped temporal conv (K=3, pad=1, 8 groups of 32 ch) ----
// y[b,l,o] = cb[o] + sum_{i<32,t<3} x[b, l+t-1, (o/32)*32 + i] * w[o,i,t]
__global__ __launch_bounds__(256) void conv_kernel(
    const float* __restrict__ qkv, const float* __restrict__ w,
    const float* __restrict__ cb, float* __restrict__ outk, float* __restrict__ outv)
{
    __shared__ float xs[18][256];
    const int b  = blockIdx.y;
    const int l0 = blockIdx.x * 16;
    const int which = blockIdx.z;
    float* out = which ? outv : outk;
    const int coff = DDIM + which * DKC;
    const int tid = threadIdx.x;

#pragma unroll
    for (int r = 0; r < 18; r++) {
        int l = l0 + r - 1;
        xs[r][tid] = (l >= 0 && l < LDIM)
                   ? qkv[((size_t)b * LDIM + l) * NQKV + coff + tid] : 0.f;
    }
    __syncthreads();

    const int o  = tid;
    const int gb = (o >> 5) << 5;     // conv-group input base
    float acc[16];
    const float bv = cb[o];
#pragma unroll
    for (int l = 0; l < 16; l++) acc[l] = bv;

    for (int i = 0; i < 32; i++) {
#pragma unroll
        for (int t = 0; t < 3; t++) {
            float wv = w[(o * 32 + i) * 3 + t];
#pragma unroll
            for (int l = 0; l < 16; l++)
                acc[l] += xs[l + t][gb + i] * wv;
        }
    }
#pragma unroll
    for (int l = 0; l < 16; l++)
        out[((size_t)b * LDIM + l0 + l) * DKC + o] = acc[l];
}

// ---------------- fused attention + attn_mean ------------------------------
// block = (b, 16-query-row tile); iterates all 16 heads (m,g) so attn_mean
// accumulates in smem without atomics. All global<->smem staging is float4;
// mainloop operand reads vectorized to minimize LDS issue pressure.
#define KB_LD 260   // padded leading dim for transposed K chunk [64][260]

extern __shared__ float smem_att[];

__global__ __launch_bounds__(256) void attn_kernel(
    const float* __restrict__ qkv, const float* __restrict__ kk,
    const float* __restrict__ vv, float* __restrict__ ctx,
    float* __restrict__ mean_out)
{
    float* s  = smem_att;            // [16][1024] scores / probs
    float* mb = s  + 16 * 1024;      // [16][1024] mean accumulator
    float* kb = mb + 16 * 1024;      // [64][260] K chunk (d-major) / [256][64] V chunk
    float* qs = kb + 64 * KB_LD;     // [16][64]
    float* ob = qs + 16 * 64;        // [4][16][64] PV partials

    const int tid = threadIdx.x;
    const int b  = blockIdx.y;
    const int l0 = blockIdx.x * 16;
    const float scale = 0.125f;      // HD^-0.5

    for (int i = tid; i < 16 * 1024 / 4; i += 256)
        *(float4*)(mb + i * 4) = make_float4(0.f, 0.f, 0.f, 0.f);

    for (int head = 0; head < 16; head++) {
        const int m = head >> 2, g = head & 3;
        const int qoff = m * 256 + g * 64;

        // load Q tile (scale folded in); one float4 per thread
        {
            int r = tid >> 4, d4 = tid & 15;
            float4 qv = *(const float4*)(
                qkv + ((size_t)b * LDIM + l0 + r) * NQKV + qoff + d4 * 4);
            qv.x *= scale; qv.y *= scale; qv.z *= scale; qv.w *= scale;
            *(float4*)(qs + r * 64 + d4 * 4) = qv;
        }

        // ---- S = Q K^T, t-chunks of 256 ----
        const int r_i = tid >> 5;    // 8 groups -> rows {2r_i, 2r_i+1}
        const int t_i = tid & 31;    // 32 groups -> 8 t each
        for (int tc = 0; tc < 4; tc++) {
            __syncthreads();
            // fill K chunk transposed: float4 LDG, scalar scatter STS
            for (int i = tid; i < 256 * 64 / 4; i += 256) {
                int t = i >> 4, d4 = i & 15;
                float4 kv = *(const float4*)(
                    kk + ((size_t)b * LDIM + tc * 256 + t) * DKC + g * 64 + d4 * 4);
                kb[(d4 * 4 + 0) * KB_LD + t] = kv.x;
                kb[(d4 * 4 + 1) * KB_LD + t] = kv.y;
                kb[(d4 * 4 + 2) * KB_LD + t] = kv.z;
                kb[(d4 * 4 + 3) * KB_LD + t] = kv.w;
            }
            __syncthreads();

            float acc0[8], acc1[8];
#pragma unroll
            for (int j = 0; j < 8; j++) { acc0[j] = 0.f; acc1[j] = 0.f; }
            const float* q0p = qs + (2 * r_i) * 64;
            const float* q1p = q0p + 64;
#pragma unroll
            for (int d4 = 0; d4 < 16; d4++) {
                // q loads vectorized (broadcast within warp: r_i warp-uniform)
                float4 q0v = *(const float4*)(q0p + d4 * 4);
                float4 q1v = *(const float4*)(q1p + d4 * 4);
#pragma unroll
                for (int dj = 0; dj < 4; dj++) {
                    float q0 = (dj == 0) ? q0v.x : (dj == 1) ? q0v.y
                             : (dj == 2) ? q0v.z : q0v.w;
                    float q1 = (dj == 0) ? q1v.x : (dj == 1) ? q1v.y
                             : (dj == 2) ? q1v.z : q1v.w;
                    const float4* kr = (const float4*)(kb + (d4 * 4 + dj) * KB_LD);
                    float4 k0 = kr[t_i * 2], k1 = kr[t_i * 2 + 1];
                    acc0[0] += q0 * k0.x; acc0[1] += q0 * k0.y;
                    acc0[2] += q0 * k0.z; acc0[3] += q0 * k0.w;
                    acc0[4] += q0 * k1.x; acc0[5] += q0 * k1.y;
                    acc0[6] += q0 * k1.z; acc0[7] += q0 * k1.w;
                    acc1[0] += q1 * k0.x; acc1[1] += q1 * k0.y;
                    acc1[2] += q1 * k0.z; acc1[3] += q1 * k0.w;
                    acc1[4] += q1 * k1.x; acc1[5] += q1 * k1.y;
                    acc1[6] += q1 * k1.z; acc1[7] += q1 * k1.w;
                }
            }
            float* s0 = s + (2 * r_i) * 1024 + tc * 256 + t_i * 8;
            *(float4*)(s0)     = make_float4(acc0[0], acc0[1], acc0[2], acc0[3]);
            *(float4*)(s0 + 4) = make_float4(acc0[4], acc0[5], acc0[6], acc0[7]);
            float* s1 = s0 + 1024;
            *(float4*)(s1)     = make_float4(acc1[0], acc1[1], acc1[2], acc1[3]);
            *(float4*)(s1 + 4) = make_float4(acc1[4], acc1[5], acc1[6], acc1[7]);
        }

        // scores for rows 2w,2w+1 were written lane-strided by warp w; sync
        // lanes before softmax reads the whole row.
        __syncwarp();

        // ---- softmax (warp w owns rows 2w, 2w+1 — same rows it computed) ----
        {
            const int w = tid >> 5, lane = tid & 31;
#pragma unroll
            for (int rr = 0; rr < 2; rr++) {
                float* srow = s + (2 * w + rr) * 1024;
                float mx = -1e30f;
                for (int j = lane; j < 1024; j += 32) mx = fmaxf(mx, srow[j]);
#pragma unroll
                for (int off = 16; off; off >>= 1)
                    mx = fmaxf(mx, __shfl_xor_sync(0xffffffffu, mx, off));
                float sum = 0.f;
                for (int j = lane; j < 1024; j += 32) {
                    float e = __expf(srow[j] - mx);
                    srow[j] = e; sum += e;
                }
#pragma unroll
                for (int off = 16; off; off >>= 1)
                    sum += __shfl_xor_sync(0xffffffffu, sum, off);
                float inv = 1.f / sum;
                float* mrow = mb + (2 * w + rr) * 1024;
                for (int j = lane; j < 1024; j += 32) {
                    float p = srow[j] * inv;
                    srow[j] = p;
                    mrow[j] += p * 0.0625f;   // /16 heads
                }
            }
        }

        // ---- O = P V, 4-way t-split, 4x4 microtile, p reads vectorized ----
        float pacc[4][4];
#pragma unroll
        for (int i = 0; i < 4; i++)
#pragma unroll
            for (int j = 0; j < 4; j++) pacc[i][j] = 0.f;
        const int ts = tid >> 6;          // t-quarter within chunk
        const int pr = (tid >> 4) & 3;    // rows pr*4 .. pr*4+3
        const int pd = tid & 15;          // cols pd*4 .. pd*4+3

        for (int tc = 0; tc < 4; tc++) {
            __syncthreads();
            // fill V chunk: float4 LDG -> float4 STS (layout-preserving)
            for (int i = tid; i < 256 * 64 / 4; i += 256) {
                int t = i >> 4, d4 = i & 15;
                float4 vv4 = *(const float4*)(
                    vv + ((size_t)b * LDIM + tc * 256 + t) * DKC + g * 64 + d4 * 4);
                *(float4*)(kb + t * 64 + d4 * 4) = vv4;
            }
            __syncthreads();
            for (int t4 = ts * 16; t4 < ts * 16 + 16; t4++) {
                const int ttb = tc * 256 + t4 * 4;
                // 4 probability rows, 4 consecutive t each (16B-aligned)
                float4 p0v = *(const float4*)(s + (pr * 4 + 0) * 1024 + ttb);
                float4 p1v = *(const float4*)(s + (pr * 4 + 1) * 1024 + ttb);
                float4 p2v = *(const float4*)(s + (pr * 4 + 2) * 1024 + ttb);
                float4 p3v = *(const float4*)(s + (pr * 4 + 3) * 1024 + ttb);
#pragma unroll
                for (int j = 0; j < 4; j++) {
                    float4 v = *(const float4*)(kb + (t4 * 4 + j) * 64 + pd * 4);
                    float p0 = (j == 0) ? p0v.x : (j == 1) ? p0v.y
                             : (j == 2) ? p0v.z : p0v.w;
                    float p1 = (j == 0) ? p1v.x : (j == 1) ? p1v.y
                             : (j == 2) ? p1v.z : p1v.w;
                    float p2 = (j == 0) ? p2v.x : (j == 1) ? p2v.y
                             : (j == 2) ? p2v.z : p2v.w;
                    float p3 = (j == 0) ? p3v.x : (j == 1) ? p3v.y
                             : (j == 2) ? p3v.z : p3v.w;
                    pacc[0][0] += p0 * v.x; pacc[0][1] += p0 * v.y;
                    pacc[0][2] += p0 * v.z; pacc[0][3] += p0 * v.w;
                    pacc[1][0] += p1 * v.x; pacc[1][1] += p1 * v.y;
                    pacc[1][2] += p1 * v.z; pacc[1][3] += p1 * v.w;
                    pacc[2][0] += p2 * v.x; pacc[2][1] += p2 * v.y;
                    pacc[2][2] += p2 * v.z; pacc[2][3] += p2 * v.w;
                    pacc[3][0] += p3 * v.x; pacc[3][1] += p3 * v.y;
                    pacc[3][2] += p3 * v.z; pacc[3][3] += p3 * v.w;
                }
            }
        }
#pragma unroll
        for (int rr = 0; rr < 4; rr++)
            *(float4*)(ob + (ts * 16 + pr * 4 + rr) * 64 + pd * 4) =
                make_float4(pacc[rr][0], pacc[rr][1], pacc[rr][2], pacc[rr][3]);
        __syncthreads();

        // reduce 4 t-split partials, write ctx (one float4 per thread)
        {
            int r = tid >> 4, d4 = tid & 15;
            float4 o0 = *(const float4*)(ob + (0 * 16 + r) * 64 + d4 * 4);
            float4 o1 = *(const float4*)(ob + (1 * 16 + r) * 64 + d4 * 4);
            float4 o2 = *(const float4*)(ob + (2 * 16 + r) * 64 + d4 * 4);
            float4 o3 = *(const float4*)(ob + (3 * 16 + r) * 64 + d4 * 4);
            float4 o;
            o.x = o0.x + o1.x + o2.x + o3.x;
            o.y = o0.y + o1.y + o2.y + o3.y;
            o.z = o0.z + o1.z + o2.z + o3.z;
            o.w = o0.w + o1.w + o2.w + o3.w;
            *(float4*)(ctx + ((size_t)b * LDIM + l0 + r) * DDIM + qoff + d4 * 4) = o;
        }
        // next head's first in-loop __syncthreads() protects s/kb reuse
    }

    __syncthreads();
    for (int i = tid; i < 16 * 1024 / 4; i += 256) {
        int r = i >> 8, t4 = i & 255;
        *(float4*)(mean_out + ((size_t)b * LDIM + l0 + r) * LDIM + t4 * 4) =
            *(const float4*)(mb + r * 1024 + t4 * 4);
    }
}

// ---------------- launch ----------------------------------------------------
extern "C" void kernel_launch(void* const* d_in, const int* in_sizes, int n_in,
                              void* d_out, int out_size)
{
    const float* query  = (const float*)d_in[0];
    // d_in[1]=key, d_in[2]=value are unused by the reference
    const float* W_qkv  = (const float*)d_in[3];
    const float* b_qkv  = (const float*)d_in[4];
    const float* conv_w = (const float*)d_in[5];
    const float* conv_b = (const float*)d_in[6];
    const float* W_out  = (const float*)d_in[7];
    const float* b_out  = (const float*)d_in[8];

    float* out      = (float*)d_out;                       // [B,L,D]
    float* mean_out = out + (size_t)ML * DDIM;             // [B,L,L]

    float *qkv, *gk, *gv, *gctx;
    cudaGetSymbolAddress((void**)&qkv,  g_qkv);
    cudaGetSymbolAddress((void**)&gk,   g_k);
    cudaGetSymbolAddress((void**)&gv,   g_v);
    cudaGetSymbolAddress((void**)&gctx, g_ctx);

    // 1) qkv projection: [8192,1024] @ [1024,1536] + bias
    sgemm_bias<<<dim3(NQKV / 128, ML / 128), 256>>>(
        query, W_qkv, b_qkv, qkv, ML, NQKV, DDIM);

    // 2) grouped temporal conv on k and v
    conv_kernel<<<dim3(LDIM / 16, BDIM, 2), 256>>>(qkv, conv_w, conv_b, gk, gv);

    // 3) fused attention (+ attn_mean written directly to output)
    static const size_t attn_smem =
        (size_t)(16 * 1024 + 16 * 1024 + 64 * KB_LD + 16 * 64 + 4 * 16 * 64) * 4;
    cudaFuncSetAttribute(attn_kernel,
                         cudaFuncAttributeMaxDynamicSharedMemorySize,
                         (int)attn_smem);
    attn_kernel<<<dim3(LDIM / 16, BDIM), 256, attn_smem>>>(
        qkv, gk, gv, gctx, mean_out);

    // 4) output projection: [8192,1024] @ [1024,1024] + bias
    sgemm_bias<<<dim3(DDIM / 128, ML / 128), 256>>>(
        gctx, W_out, b_out, out, ML, DDIM, DDIM);
}

// round 15
// speedup vs baseline: 1.7113x; 1.7113x over previous
#include <cuda_runtime.h>
#include <math.h>
#include <stdint.h>

// ---------------- problem constants ----------------
#define BDIM   8
#define LDIM   1024
#define DDIM   1024
#define HDIM   64
#define DKC    256          // D / G
#define NQKV   1536         // D + 2*DK
#define ML     (BDIM*LDIM)  // 8192 rows

// ---------------- scratch (__device__ globals; no allocs allowed) ----------
__device__ float g_qkv[(size_t)ML * NQKV];   // qkv projection output
__device__ float g_k  [(size_t)ML * DKC];    // conv'd k
__device__ float g_v  [(size_t)ML * DKC];    // conv'd v
__device__ float g_ctx[(size_t)ML * DDIM];   // attention context (pre W_out)

// ---------------- tf32 helpers --------------------------------------------
__device__ __forceinline__ uint32_t f2tf(float f) {
    uint32_t u;
    asm("cvt.rna.tf32.f32 %0, %1;" : "=r"(u) : "f"(f));
    return u;
}
__device__ __forceinline__ float f2tff(float f) { return __uint_as_float(f2tf(f)); }
__device__ __forceinline__ uint32_t fau(float f) { return __float_as_uint(f); }

// D(m16n8) += A(m16k8,row) * B(k8n8,col); fp32 accum
__device__ __forceinline__ void mma_tf32(float c[4],
    uint32_t a0, uint32_t a1, uint32_t a2, uint32_t a3,
    uint32_t b0, uint32_t b1)
{
    asm volatile(
        "mma.sync.aligned.m16n8k8.row.col.f32.tf32.tf32.f32 "
        "{%0,%1,%2,%3}, {%4,%5,%6,%7}, {%8,%9}, {%0,%1,%2,%3};"
        : "+f"(c[0]), "+f"(c[1]), "+f"(c[2]), "+f"(c[3])
        : "r"(a0), "r"(a1), "r"(a2), "r"(a3), "r"(b0), "r"(b1));
}

// ---------------- tf32 tensor-core GEMM: C = A[MxK]*W[KxN] + bias ----------
// CTA 128x128, BK=16, 8 warps (2m x 4n), warp tile 64x32, double-buffered.
#define AS_LD 20    // (20*g+tg) mod 32 distinct -> conflict-free a-frags
#define BS_LD 136   // (8*tg+g)  mod 32 distinct -> conflict-free b-frags
__global__ __launch_bounds__(256) void gemm_tf32(
    const float* __restrict__ A, const float* __restrict__ W,
    const float* __restrict__ bias, float* __restrict__ C,
    int M, int N, int K)
{
    __shared__ float As[2][128][AS_LD];
    __shared__ float Bs[2][16][BS_LD];
    const int tid  = threadIdx.x;
    const int wid  = tid >> 5, lane = tid & 31;
    const int wm   = wid >> 2, wn = wid & 3;
    const int g    = lane >> 2, tg = lane & 3;
    const int bm   = blockIdx.y * 128, bn = blockIdx.x * 128;

    float c[4][4][4];
#pragma unroll
    for (int mt = 0; mt < 4; mt++)
#pragma unroll
        for (int nt = 0; nt < 4; nt++)
#pragma unroll
            for (int i = 0; i < 4; i++) c[mt][nt][i] = 0.f;

    const int aRow = tid >> 2, aq = tid & 3;
    const int bkr0 = tid >> 5,        bn40 = tid & 31;
    const int bkr1 = (tid + 256) >> 5, bn41 = tid & 31;  // +256 keeps n4
    const float* aP0 = A + (size_t)(bm + aRow) * K + aq * 4;
    const float* aP1 = A + (size_t)(bm + aRow + 64) * K + aq * 4;
    const float* bP0 = W + (size_t)bkr0 * N + bn + bn40 * 4;
    const float* bP1 = W + (size_t)bkr1 * N + bn + bn41 * 4;

    float4 va0 = *(const float4*)(aP0);
    float4 va1 = *(const float4*)(aP1);
    float4 vb0 = *(const float4*)(bP0);
    float4 vb1 = *(const float4*)(bP1);
    {   // store tile 0
        float* p;
        p = &As[0][aRow][aq * 4];
        p[0]=f2tff(va0.x); p[1]=f2tff(va0.y); p[2]=f2tff(va0.z); p[3]=f2tff(va0.w);
        p = &As[0][aRow + 64][aq * 4];
        p[0]=f2tff(va1.x); p[1]=f2tff(va1.y); p[2]=f2tff(va1.z); p[3]=f2tff(va1.w);
        p = &Bs[0][bkr0][bn40 * 4];
        p[0]=f2tff(vb0.x); p[1]=f2tff(vb0.y); p[2]=f2tff(vb0.z); p[3]=f2tff(vb0.w);
        p = &Bs[0][bkr1][bn41 * 4];
        p[0]=f2tff(vb1.x); p[1]=f2tff(vb1.y); p[2]=f2tff(vb1.z); p[3]=f2tff(vb1.w);
    }
    __syncthreads();

    int buf = 0;
    for (int k0 = 0; k0 < K; k0 += 16) {
        const bool hn = (k0 + 16) < K;
        if (hn) {
            va0 = *(const float4*)(aP0 + k0 + 16);
            va1 = *(const float4*)(aP1 + k0 + 16);
            vb0 = *(const float4*)(bP0 + (size_t)(k0 + 16) * N);
            vb1 = *(const float4*)(bP1 + (size_t)(k0 + 16) * N);
        }
#pragma unroll
        for (int ks = 0; ks < 2; ks++) {
            uint32_t af[4][4], bf[4][2];
#pragma unroll
            for (int mt = 0; mt < 4; mt++) {
                const float* ap = &As[buf][wm * 64 + mt * 16 + g][ks * 8 + tg];
                af[mt][0] = fau(ap[0]);
                af[mt][1] = fau(ap[8 * AS_LD]);
                af[mt][2] = fau(ap[4]);
                af[mt][3] = fau(ap[8 * AS_LD + 4]);
            }
#pragma unroll
            for (int nt = 0; nt < 4; nt++) {
                const float* bp = &Bs[buf][ks * 8 + tg][wn * 32 + nt * 8 + g];
                bf[nt][0] = fau(bp[0]);
                bf[nt][1] = fau(bp[4 * BS_LD]);
            }
#pragma unroll
            for (int mt = 0; mt < 4; mt++)
#pragma unroll
                for (int nt = 0; nt < 4; nt++)
                    mma_tf32(c[mt][nt], af[mt][0], af[mt][1], af[mt][2], af[mt][3],
                             bf[nt][0], bf[nt][1]);
        }
        if (hn) {
            const int nb = buf ^ 1;
            float* p;
            p = &As[nb][aRow][aq * 4];
            p[0]=f2tff(va0.x); p[1]=f2tff(va0.y); p[2]=f2tff(va0.z); p[3]=f2tff(va0.w);
            p = &As[nb][aRow + 64][aq * 4];
            p[0]=f2tff(va1.x); p[1]=f2tff(va1.y); p[2]=f2tff(va1.z); p[3]=f2tff(va1.w);
            p = &Bs[nb][bkr0][bn40 * 4];
            p[0]=f2tff(vb0.x); p[1]=f2tff(vb0.y); p[2]=f2tff(vb0.z); p[3]=f2tff(vb0.w);
            p = &Bs[nb][bkr1][bn41 * 4];
            p[0]=f2tff(vb1.x); p[1]=f2tff(vb1.y); p[2]=f2tff(vb1.z); p[3]=f2tff(vb1.w);
            __syncthreads();
            buf = nb;
        }
    }

#pragma unroll
    for (int mt = 0; mt < 4; mt++)
#pragma unroll
        for (int nt = 0; nt < 4; nt++) {
            const int row0 = bm + wm * 64 + mt * 16 + g;
            const int col  = bn + wn * 32 + nt * 8 + 2 * tg;
            const float b0 = bias[col], b1 = bias[col + 1];
            *(float2*)(C + (size_t)row0 * N + col) =
                make_float2(c[mt][nt][0] + b0, c[mt][nt][1] + b1);
            *(float2*)(C + (size_t)(row0 + 8) * N + col) =
                make_float2(c[mt][nt][2] + b0, c[mt][nt][3] + b1);
        }
}

// ---------------- grouped temporal conv (K=3, pad=1, 8 groups of 32 ch) ----
__global__ __launch_bounds__(256) void conv_kernel(
    const float* __restrict__ qkv, const float* __restrict__ w,
    const float* __restrict__ cb, float* __restrict__ outk, float* __restrict__ outv)
{
    __shared__ float xs[18][256];
    const int b  = blockIdx.y;
    const int l0 = blockIdx.x * 16;
    const int which = blockIdx.z;
    float* out = which ? outv : outk;
    const int coff = DDIM + which * DKC;
    const int tid = threadIdx.x;

#pragma unroll
    for (int r = 0; r < 18; r++) {
        int l = l0 + r - 1;
        xs[r][tid] = (l >= 0 && l < LDIM)
                   ? qkv[((size_t)b * LDIM + l) * NQKV + coff + tid] : 0.f;
    }
    __syncthreads();

    const int o  = tid;
    const int gb = (o >> 5) << 5;
    float acc[16];
    const float bv = cb[o];
#pragma unroll
    for (int l = 0; l < 16; l++) acc[l] = bv;

    for (int i = 0; i < 32; i++) {
#pragma unroll
        for (int t = 0; t < 3; t++) {
            float wv = w[(o * 32 + i) * 3 + t];
#pragma unroll
            for (int l = 0; l < 16; l++)
                acc[l] += xs[l + t][gb + i] * wv;
        }
    }
#pragma unroll
    for (int l = 0; l < 16; l++)
        out[((size_t)b * LDIM + l0 + l) * DKC + o] = acc[l];
}

// ---------------- fused attention + attn_mean (tf32 tensor cores) ----------
// block = (b, 16 query rows); 16 heads sequentially; mean kept in REGISTERS
// (thread (w,lane) owns rows {2w,2w+1} x cols {lane+32k}), staged via smem at
// the end. QK: warp w owns t-range [32w,32w+32); PV: warp w owns d-cols
// [8w,8w+8) with accumulators resident in registers across chunks.
// kb strides are PHASE-SPECIFIC: K chunks use K_LD=76 (QK b-frags {12g+tg}
// conflict-free), V chunks use V_LD=72 (PV b-frags {8tg+g} conflict-free).
#define S_LD  1028  // mod32=4: PV a-frags conflict-free; float4-aligned
#define K_LD  76    // QK phase
#define V_LD  72    // PV phase
#define Q_LD  68    // mod32=4: QK a-frags conflict-free

extern __shared__ float smem_att[];

__global__ __launch_bounds__(256) void attn_kernel(
    const float* __restrict__ qkv, const float* __restrict__ kk,
    const float* __restrict__ vv, float* __restrict__ ctx,
    float* __restrict__ mean_out)
{
    float* s  = smem_att;                 // [16][S_LD]
    float* kb = s + 16 * S_LD;            // [256][K_LD] K  /  [256][V_LD] V
    float* qs = kb + 256 * K_LD;          // [16][Q_LD]   Q (tf32, scaled)

    const int tid  = threadIdx.x;
    const int w    = tid >> 5, lane = tid & 31;
    const int g    = lane >> 2, tg = lane & 3;
    const int b    = blockIdx.y;
    const int l0   = blockIdx.x * 16;
    const float scale = 0.125f;

    float m_acc[2][32];
#pragma unroll
    for (int rr = 0; rr < 2; rr++)
#pragma unroll
        for (int j = 0; j < 32; j++) m_acc[rr][j] = 0.f;

    for (int head = 0; head < 16; head++) {
        const int m = head >> 2, gq = head & 3;
        const int qoff = m * 256 + gq * 64;

        // ---- load Q tile, scale, convert to tf32 ----
        {
            int r = tid >> 4, d4 = tid & 15;
            float4 qv = *(const float4*)(
                qkv + ((size_t)b * LDIM + l0 + r) * NQKV + qoff + d4 * 4);
            float4 cv = make_float4(f2tff(qv.x * scale), f2tff(qv.y * scale),
                                    f2tff(qv.z * scale), f2tff(qv.w * scale));
            *(float4*)(qs + r * Q_LD + d4 * 4) = cv;
        }
        __syncthreads();   // qs visible; all warps done with prior head

        // ---- Q fragments (8 k-steps), resident for whole head ----
        uint32_t aq[8][4];
#pragma unroll
        for (int ks = 0; ks < 8; ks++) {
            const float* ap = &qs[g * Q_LD + ks * 8 + tg];
            aq[ks][0] = fau(ap[0]);
            aq[ks][1] = fau(ap[8 * Q_LD]);
            aq[ks][2] = fau(ap[4]);
            aq[ks][3] = fau(ap[8 * Q_LD + 4]);
        }

        // ---- S = Q K^T over 4 t-chunks of 256 ----
        for (int tc = 0; tc < 4; tc++) {
            __syncthreads();   // kb free (prior chunk mma / prior head done)
            for (int i = tid; i < 256 * 16; i += 256) {
                int t = i >> 4, d4 = i & 15;
                float4 kv = *(const float4*)(
                    kk + ((size_t)b * LDIM + tc * 256 + t) * DKC + gq * 64 + d4 * 4);
                float4 cv = make_float4(f2tff(kv.x), f2tff(kv.y),
                                        f2tff(kv.z), f2tff(kv.w));
                *(float4*)(kb + t * K_LD + d4 * 4) = cv;
            }
            __syncthreads();

            float cqk[4][4];
#pragma unroll
            for (int nt = 0; nt < 4; nt++)
#pragma unroll
                for (int i = 0; i < 4; i++) cqk[nt][i] = 0.f;
#pragma unroll
            for (int ks = 0; ks < 8; ks++)
#pragma unroll
                for (int nt = 0; nt < 4; nt++) {
                    const float* bp = &kb[(w * 32 + nt * 8 + g) * K_LD + ks * 8 + tg];
                    mma_tf32(cqk[nt], aq[ks][0], aq[ks][1], aq[ks][2], aq[ks][3],
                             fau(bp[0]), fau(bp[4]));
                }
#pragma unroll
            for (int nt = 0; nt < 4; nt++) {
                int tcol = tc * 256 + w * 32 + nt * 8 + 2 * tg;
                *(float2*)(s + g * S_LD + tcol) =
                    make_float2(cqk[nt][0], cqk[nt][1]);
                *(float2*)(s + (g + 8) * S_LD + tcol) =
                    make_float2(cqk[nt][2], cqk[nt][3]);
            }
        }
        __syncthreads();   // S complete across warps

        // ---- softmax on rows 2w, 2w+1; p stored tf32; mean in registers ----
#pragma unroll
        for (int rr = 0; rr < 2; rr++) {
            float* srow = s + (2 * w + rr) * S_LD;
            float mx = -1e30f;
#pragma unroll
            for (int j = 0; j < 32; j++) mx = fmaxf(mx, srow[lane + 32 * j]);
#pragma unroll
            for (int off = 16; off; off >>= 1)
                mx = fmaxf(mx, __shfl_xor_sync(0xffffffffu, mx, off));
            float sum = 0.f;
#pragma unroll
            for (int j = 0; j < 32; j++) {
                float e = __expf(srow[lane + 32 * j] - mx);
                srow[lane + 32 * j] = e; sum += e;
            }
#pragma unroll
            for (int off = 16; off; off >>= 1)
                sum += __shfl_xor_sync(0xffffffffu, sum, off);
            float inv = 1.f / sum;
#pragma unroll
            for (int j = 0; j < 32; j++) {
                float p = srow[lane + 32 * j] * inv;
                srow[lane + 32 * j] = f2tff(p);
                m_acc[rr][j] += p * 0.0625f;
            }
        }

        // ---- O = P V; warp w owns d-cols [8w,8w+8); acc in registers ----
        float o[4] = {0.f, 0.f, 0.f, 0.f};
        for (int tc = 0; tc < 4; tc++) {
            __syncthreads();   // tc=0: softmax p-writes visible; kb free
            for (int i = tid; i < 256 * 16; i += 256) {
                int t = i >> 4, d4 = i & 15;
                float4 v4 = *(const float4*)(
                    vv + ((size_t)b * LDIM + tc * 256 + t) * DKC + gq * 64 + d4 * 4);
                float4 cv = make_float4(f2tff(v4.x), f2tff(v4.y),
                                        f2tff(v4.z), f2tff(v4.w));
                *(float4*)(kb + t * V_LD + d4 * 4) = cv;
            }
            __syncthreads();
#pragma unroll
            for (int ks = 0; ks < 32; ks++) {
                const float* ap = &s[g * S_LD + tc * 256 + ks * 8 + tg];
                const float* bp = &kb[(ks * 8 + tg) * V_LD + w * 8 + g];
                mma_tf32(o, fau(ap[0]), fau(ap[8 * S_LD]),
                            fau(ap[4]), fau(ap[8 * S_LD + 4]),
                            fau(bp[0]), fau(bp[4 * V_LD]));
            }
        }
        {
            const int col = qoff + w * 8 + 2 * tg;
            *(float2*)(ctx + ((size_t)b * LDIM + l0 + g) * DDIM + col) =
                make_float2(o[0], o[1]);
            *(float2*)(ctx + ((size_t)b * LDIM + l0 + g + 8) * DDIM + col) =
                make_float2(o[2], o[3]);
        }
    }

    // ---- stage register mean through smem, write coalesced ----
    __syncthreads();
#pragma unroll
    for (int rr = 0; rr < 2; rr++)
#pragma unroll
        for (int j = 0; j < 32; j++)
            kb[(2 * w + rr) * 1024 + lane + 32 * j] = m_acc[rr][j];
    __syncthreads();
    for (int i = tid; i < 4096; i += 256) {
        int r = i >> 8, t4 = i & 255;
        *(float4*)(mean_out + ((size_t)b * LDIM + l0 + r) * LDIM + t4 * 4) =
            *(const float4*)(kb + r * 1024 + t4 * 4);
    }
}

// ---------------- launch ----------------------------------------------------
extern "C" void kernel_launch(void* const* d_in, const int* in_sizes, int n_in,
                              void* d_out, int out_size)
{
    const float* query  = (const float*)d_in[0];
    const float* W_qkv  = (const float*)d_in[3];
    const float* b_qkv  = (const float*)d_in[4];
    const float* conv_w = (const float*)d_in[5];
    const float* conv_b = (const float*)d_in[6];
    const float* W_out  = (const float*)d_in[7];
    const float* b_out  = (const float*)d_in[8];

    float* out      = (float*)d_out;
    float* mean_out = out + (size_t)ML * DDIM;

    float *qkv, *gk, *gv, *gctx;
    cudaGetSymbolAddress((void**)&qkv,  g_qkv);
    cudaGetSymbolAddress((void**)&gk,   g_k);
    cudaGetSymbolAddress((void**)&gv,   g_v);
    cudaGetSymbolAddress((void**)&gctx, g_ctx);

    // 1) qkv projection (tf32 tensor cores)
    gemm_tf32<<<dim3(NQKV / 128, ML / 128), 256>>>(
        query, W_qkv, b_qkv, qkv, ML, NQKV, DDIM);

    // 2) grouped temporal conv on k and v
    conv_kernel<<<dim3(LDIM / 16, BDIM, 2), 256>>>(qkv, conv_w, conv_b, gk, gv);

    // 3) fused attention (+ attn_mean)
    static const size_t attn_smem =
        (size_t)(16 * S_LD + 256 * K_LD + 16 * Q_LD) * 4;
    cudaFuncSetAttribute(attn_kernel,
                         cudaFuncAttributeMaxDynamicSharedMemorySize,
                         (int)attn_smem);
    attn_kernel<<<dim3(LDIM / 16, BDIM), 256, attn_smem>>>(
        qkv, gk, gv, gctx, mean_out);

    // 4) output projection (tf32 tensor cores)
    gemm_tf32<<<dim3(DDIM / 128, ML / 128), 256>>>(
        gctx, W_out, b_out, out, ML, DDIM, DDIM);
}